// round 6
// baseline (speedup 1.0000x reference)
#include <cuda_runtime.h>

// ---------------------------------------------------------------------------
// GAT layer, CSR-gather version, f32x2 GEMM:
//   1. detect idx dtype, zero degree counters
//   2. counting sort edges by dst: histogram -> multi-block scan -> scatter
//   3. QKV GEMM (fused 3-in-1, packed fma.rn.f32x2 inner loop)
//   4. aggregate: warp per dst; gather K/V[src], softmax accumulate in regs
//   5. output GEMM + bias + relu
// ---------------------------------------------------------------------------

#define MAXN 50048
#define MAXE 1600000
#define SCAN_BLK 1024
#define MAX_SBLKS 64

__device__ float g_Q[MAXN * 128];
__device__ float g_K[MAXN * 128];
__device__ float g_V[MAXN * 128];
__device__ float g_agg[MAXN * 128];
__device__ int   g_off[MAXN + 1];   // CSR row starts
__device__ int   g_cur[MAXN];       // scatter cursors; == row end after sort
__device__ int   g_srcs[MAXE];      // src ids sorted by dst
__device__ int   g_bsum[MAX_SBLKS]; // per-block sums for scan
__device__ int   g_idx64;           // 1 if edge_index is int64, 0 if int32

__device__ __forceinline__ int load_idx(const void* ei, long long pos, int M) {
    int v;
    if (g_idx64) v = (int)((const long long*)ei)[pos];
    else         v = ((const int*)ei)[pos];
    v = v < 0 ? 0 : (v >= M ? M - 1 : v);   // defensive clamp
    return v;
}

// ---------------------------------------------------------------------------
__global__ void detect_kernel(const unsigned* __restrict__ ei_u32) {
    if (threadIdx.x == 0 && blockIdx.x == 0) {
        int is64 = 1;
        for (int i = 0; i < 128; i++)
            if (ei_u32[2 * i + 1] != 0u) { is64 = 0; break; }
        g_idx64 = is64;
    }
}

__global__ void zero_deg(int M) {
    int t = blockIdx.x * blockDim.x + threadIdx.x;
    if (t < M) g_off[t] = 0;          // reuse g_off as degree counter
}

// histogram of dst
__global__ void hist_kernel(const void* __restrict__ ei, int E, int M) {
    int t = blockIdx.x * blockDim.x + threadIdx.x;
    if (t >= E) return;
    int dst = load_idx(ei, (long long)E + t, M);
    atomicAdd(&g_off[dst], 1);
}

// ---------------------------------------------------------------------------
// Multi-block exclusive scan of g_off[0..M) (degrees -> offsets).
// ---------------------------------------------------------------------------
__global__ void scan_partial(int M) {
    __shared__ int wsum[32];
    int tid  = threadIdx.x;
    int gi   = blockIdx.x * SCAN_BLK + tid;
    int lane = tid & 31;
    int wid  = tid >> 5;

    int v = (gi < M) ? g_off[gi] : 0;

    int x = v;
#pragma unroll
    for (int o = 1; o < 32; o <<= 1) {
        int y = __shfl_up_sync(0xFFFFFFFFu, x, o);
        if (lane >= o) x += y;
    }
    if (lane == 31) wsum[wid] = x;
    __syncthreads();

    if (wid == 0) {
        int w = wsum[lane];
#pragma unroll
        for (int o = 1; o < 32; o <<= 1) {
            int y = __shfl_up_sync(0xFFFFFFFFu, w, o);
            if (lane >= o) w += y;
        }
        wsum[lane] = w;
    }
    __syncthreads();

    int incl = x + (wid > 0 ? wsum[wid - 1] : 0);
    int excl = incl - v;
    if (gi < M) g_off[gi] = excl;        // block-local exclusive for now
    if (tid == SCAN_BLK - 1) g_bsum[blockIdx.x] = incl;
}

// exclusive scan of block sums (nb <= 63); stores total at g_bsum[nb]
__global__ void scan_bsums(int nb) {
    __shared__ int s[MAX_SBLKS];
    int lane = threadIdx.x;
    if (lane < MAX_SBLKS) s[lane] = (lane < nb) ? g_bsum[lane] : 0;
    __syncthreads();
    if (lane == 0) {
        int run = 0;
        for (int i = 0; i < nb; i++) { int t = s[i]; s[i] = run; run += t; }
        s[nb] = run;
    }
    __syncthreads();
    if (lane <= nb) g_bsum[lane] = s[lane];
}

// add block offsets; init cursors; set g_off[M] = total
__global__ void scan_add(int M) {
    int tid = threadIdx.x;
    int gi  = blockIdx.x * SCAN_BLK + tid;
    if (gi < M) {
        int o = g_off[gi] + g_bsum[blockIdx.x];
        g_off[gi] = o;
        g_cur[gi] = o;
    }
    if (gi == M) {
        int nb = (M + SCAN_BLK - 1) / SCAN_BLK;
        g_off[M] = g_bsum[nb];
    }
}

// scatter src ids into dst-sorted order
__global__ void scatter_kernel(const void* __restrict__ ei, int E, int M) {
    int t = blockIdx.x * blockDim.x + threadIdx.x;
    if (t >= E) return;
    int src = load_idx(ei, t, M);
    int dst = load_idx(ei, (long long)E + t, M);
    int pos = atomicAdd(&g_cur[dst], 1);
    g_srcs[pos] = src;
}

// ---------------------------------------------------------------------------
// Tiled fp32 GEMM with packed fma.rn.f32x2 inner loop.
// C[M,128] = A[M,128] @ B[128,128]^T + bias (+relu).
// blockIdx.y selects among up to 3 (B, bias, C) triples (fused QKV).
// ---------------------------------------------------------------------------
#define BM 128
#define BN 128
#define BK 32

#define PACK2(d, lo, hi) asm("mov.b64 %0, {%1,%2};" : "=l"(d) : "f"(lo), "f"(hi))
#define PACKBC(d, v)     asm("mov.b64 %0, {%1,%1};" : "=l"(d) : "f"(v))
#define FMA2(acc, a, b)  asm("fma.rn.f32x2 %0, %1, %2, %0;" : "+l"(acc) : "l"(a), "l"(b))
#define UNPACK2(lo, hi, d) asm("mov.b64 {%0,%1}, %2;" : "=f"(lo), "=f"(hi) : "l"(d))

__global__ __launch_bounds__(256, 2)
void gemm_kernel(const float* __restrict__ A, int M,
                 const float* __restrict__ Ba, const float* __restrict__ Bb,
                 const float* __restrict__ Bc,
                 const float* __restrict__ ba, const float* __restrict__ bb,
                 const float* __restrict__ bc,
                 float* __restrict__ Ca, float* __restrict__ Cb,
                 float* __restrict__ Cc,
                 int relu)
{
    __shared__ float As[BK][BM + 4];
    __shared__ float Bs[BK][BN + 4];

    const float* B;
    const float* bias;
    float*       C;
    if (blockIdx.y == 0)      { B = Ba; bias = ba; C = Ca; }
    else if (blockIdx.y == 1) { B = Bb; bias = bb; C = Cb; }
    else                      { B = Bc; bias = bc; C = Cc; }

    int tid = threadIdx.x;
    int tx  = tid & 15;
    int ty  = tid >> 4;
    int m0  = blockIdx.x * BM;

    // 8x8 accumulator as 8x4 packed f32x2 pairs (cols c,c+1)
    unsigned long long accp[8][4];
#pragma unroll
    for (int r = 0; r < 8; r++)
#pragma unroll
        for (int c = 0; c < 4; c++) accp[r][c] = 0ULL;

    for (int k0 = 0; k0 < 128; k0 += BK) {
#pragma unroll
        for (int i = 0; i < 4; i++) {
            int idx = tid + i * 256;     // 0..1023
            int row = idx & 127;
            int kq  = idx >> 7;          // 0..7
            float4 v = make_float4(0.f, 0.f, 0.f, 0.f);
            int m = m0 + row;
            if (m < M)
                v = *(const float4*)(A + (size_t)m * 128 + k0 + kq * 4);
            As[kq * 4 + 0][row] = v.x;
            As[kq * 4 + 1][row] = v.y;
            As[kq * 4 + 2][row] = v.z;
            As[kq * 4 + 3][row] = v.w;
            float4 w = *(const float4*)(B + (size_t)row * 128 + k0 + kq * 4);
            Bs[kq * 4 + 0][row] = w.x;
            Bs[kq * 4 + 1][row] = w.y;
            Bs[kq * 4 + 2][row] = w.z;
            Bs[kq * 4 + 3][row] = w.w;
        }
        __syncthreads();

#pragma unroll
        for (int kk = 0; kk < BK; kk++) {
            float4 a0 = *(const float4*)&As[kk][ty * 8];
            float4 a1 = *(const float4*)&As[kk][ty * 8 + 4];
            float4 b0 = *(const float4*)&Bs[kk][tx * 8];
            float4 b1 = *(const float4*)&Bs[kk][tx * 8 + 4];

            unsigned long long bp[4];
            PACK2(bp[0], b0.x, b0.y);
            PACK2(bp[1], b0.z, b0.w);
            PACK2(bp[2], b1.x, b1.y);
            PACK2(bp[3], b1.z, b1.w);

            float a[8] = {a0.x, a0.y, a0.z, a0.w, a1.x, a1.y, a1.z, a1.w};
#pragma unroll
            for (int r = 0; r < 8; r++) {
                unsigned long long ap;
                PACKBC(ap, a[r]);
#pragma unroll
                for (int c = 0; c < 4; c++)
                    FMA2(accp[r][c], ap, bp[c]);
            }
        }
        __syncthreads();
    }

#pragma unroll
    for (int r = 0; r < 8; r++) {
        int m = m0 + ty * 8 + r;
        if (m >= M) continue;
#pragma unroll
        for (int c = 0; c < 8; c += 4) {
            int n = tx * 8 + c;
            float e0, e1, e2, e3;
            UNPACK2(e0, e1, accp[r][c / 2 + 0 + (c >= 4 ? 0 : 0)]);
            UNPACK2(e2, e3, accp[r][c / 2 + 1]);
            float4 o;
            o.x = e0 + bias[n + 0];
            o.y = e1 + bias[n + 1];
            o.z = e2 + bias[n + 2];
            o.w = e3 + bias[n + 3];
            if (relu) {
                o.x = fmaxf(o.x, 0.f);
                o.y = fmaxf(o.y, 0.f);
                o.z = fmaxf(o.z, 0.f);
                o.w = fmaxf(o.w, 0.f);
            }
            *(float4*)(C + (size_t)m * 128 + n) = o;
        }
    }
}

// ---------------------------------------------------------------------------
// Warp per dst node: softmax-weighted aggregation of V[src] over CSR edges.
// ---------------------------------------------------------------------------
__device__ __forceinline__ void edge_step(int sj, const float4& q,
                                          float4& acc, float& ssum, int lane)
{
    float4 k = ((const float4*)(g_K + (size_t)sj * 128))[lane];
    float4 v = ((const float4*)(g_V + (size_t)sj * 128))[lane];
    float part = q.x * k.x + q.y * k.y + q.z * k.z + q.w * k.w;
    part += __shfl_xor_sync(0xFFFFFFFFu, part, 1);
    part += __shfl_xor_sync(0xFFFFFFFFu, part, 2);
    part += __shfl_xor_sync(0xFFFFFFFFu, part, 4);
    float p = expf(part * 0.17677669529663687f);
    acc.x = fmaf(p, v.x, acc.x);
    acc.y = fmaf(p, v.y, acc.y);
    acc.z = fmaf(p, v.z, acc.z);
    acc.w = fmaf(p, v.w, acc.w);
    ssum += p;
}

__global__ __launch_bounds__(256)
void aggregate_kernel(int M)
{
    int w    = (int)(((long long)blockIdx.x * blockDim.x + threadIdx.x) >> 5);
    int lane = threadIdx.x & 31;
    if (w >= M) return;

    int start = g_off[w];
    int end   = g_cur[w];    // == g_off[w+1] after scatter

    float4 q = ((const float4*)(g_Q + (size_t)w * 128))[lane];
    float4 acc = make_float4(0.f, 0.f, 0.f, 0.f);
    float ssum = 0.f;

    int i = start;
    for (; i + 32 <= end; i += 32) {
        int s = g_srcs[i + lane];
#pragma unroll 4
        for (int j = 0; j < 32; j++) {
            int sj = __shfl_sync(0xFFFFFFFFu, s, j);
            edge_step(sj, q, acc, ssum, lane);
        }
    }
    if (i < end) {
        int rem = end - i;
        int s = (lane < rem) ? g_srcs[i + lane] : 0;
        for (int j = 0; j < rem; j++) {
            int sj = __shfl_sync(0xFFFFFFFFu, s, j);
            edge_step(sj, q, acc, ssum, lane);
        }
    }

    float inv = 1.f / (ssum + 1e-8f);
    float4 o = make_float4(acc.x * inv, acc.y * inv, acc.z * inv, acc.w * inv);
    ((float4*)(g_agg + (size_t)w * 128))[lane] = o;
}

// ---------------------------------------------------------------------------
extern "C" void kernel_launch(void* const* d_in, const int* in_sizes, int n_in,
                              void* d_out, int out_size)
{
    const float* x  = (const float*)d_in[0];
    const void*  ei = d_in[1];
    const float* Wq = (const float*)d_in[2];
    const float* bq = (const float*)d_in[3];
    const float* Wk = (const float*)d_in[4];
    const float* bk = (const float*)d_in[5];
    const float* Wv = (const float*)d_in[6];
    const float* bv = (const float*)d_in[7];
    const float* Wo = (const float*)d_in[8];
    const float* bo = (const float*)d_in[9];
    float*       out = (float*)d_out;

    int M = in_sizes[0] / 128;   // nodes
    int E = in_sizes[1] / 2;     // edges

    float *pQ, *pK, *pV, *pAgg;
    cudaGetSymbolAddress((void**)&pQ,   g_Q);
    cudaGetSymbolAddress((void**)&pK,   g_K);
    cudaGetSymbolAddress((void**)&pV,   g_V);
    cudaGetSymbolAddress((void**)&pAgg, g_agg);

    int nb = (M + SCAN_BLK - 1) / SCAN_BLK;   // 49 for M=50000

    detect_kernel<<<1, 32>>>((const unsigned*)ei);
    zero_deg<<<(M + 255) / 256, 256>>>(M);
    hist_kernel<<<(E + 255) / 256, 256>>>(ei, E, M);
    scan_partial<<<nb, SCAN_BLK>>>(M);
    scan_bsums<<<1, MAX_SBLKS>>>(nb);
    scan_add<<<nb + 1, SCAN_BLK>>>(M);
    scatter_kernel<<<(E + 255) / 256, 256>>>(ei, E, M);

    dim3 gqkv((M + BM - 1) / BM, 3);
    gemm_kernel<<<gqkv, 256>>>(x, M, Wq, Wk, Wv, bq, bk, bv, pQ, pK, pV, 0);

    long long wt = (long long)M * 32;
    aggregate_kernel<<<(int)((wt + 255) / 256), 256>>>(M);

    dim3 gout((M + BM - 1) / BM, 1);
    gemm_kernel<<<gout, 256>>>(pAgg, M, Wo, Wo, Wo, bo, bo, bo, out, out, out, 1);
}

// round 7
// speedup vs baseline: 1.2505x; 1.2505x over previous
#include <cuda_runtime.h>

// ---------------------------------------------------------------------------
// GAT layer, CSR-gather + tf32 tensor-core GEMM (3-term hi/lo split ~ fp32):
//   1. detect idx dtype, zero degree counters
//   2. counting sort edges by dst: histogram -> multi-block scan -> scatter
//   3. QKV GEMM (fused 3-in-1, mma.sync.m16n8k8.tf32, hi*hi+hi*lo+lo*hi)
//   4. aggregate: warp per dst; gather K/V[src], softmax accumulate in regs
//   5. output GEMM + bias + relu (same tf32 kernel)
// ---------------------------------------------------------------------------

#define MAXN 50048
#define MAXE 1600000
#define SCAN_BLK 1024
#define MAX_SBLKS 64

__device__ float g_Q[MAXN * 128];
__device__ float g_K[MAXN * 128];
__device__ float g_V[MAXN * 128];
__device__ float g_agg[MAXN * 128];
__device__ int   g_off[MAXN + 1];   // CSR row starts
__device__ int   g_cur[MAXN];       // scatter cursors; == row end after sort
__device__ int   g_srcs[MAXE];      // src ids sorted by dst
__device__ int   g_bsum[MAX_SBLKS]; // per-block sums for scan
__device__ int   g_idx64;           // 1 if edge_index is int64, 0 if int32

__device__ __forceinline__ int load_idx(const void* ei, long long pos, int M) {
    int v;
    if (g_idx64) v = (int)((const long long*)ei)[pos];
    else         v = ((const int*)ei)[pos];
    v = v < 0 ? 0 : (v >= M ? M - 1 : v);   // defensive clamp
    return v;
}

// ---------------------------------------------------------------------------
__global__ void detect_kernel(const unsigned* __restrict__ ei_u32) {
    if (threadIdx.x == 0 && blockIdx.x == 0) {
        int is64 = 1;
        for (int i = 0; i < 128; i++)
            if (ei_u32[2 * i + 1] != 0u) { is64 = 0; break; }
        g_idx64 = is64;
    }
}

__global__ void zero_deg(int M) {
    int t = blockIdx.x * blockDim.x + threadIdx.x;
    if (t < M) g_off[t] = 0;          // reuse g_off as degree counter
}

__global__ void hist_kernel(const void* __restrict__ ei, int E, int M) {
    int t = blockIdx.x * blockDim.x + threadIdx.x;
    if (t >= E) return;
    int dst = load_idx(ei, (long long)E + t, M);
    atomicAdd(&g_off[dst], 1);
}

// ---------------------------------------------------------------------------
// Multi-block exclusive scan of g_off[0..M) (degrees -> offsets).
// ---------------------------------------------------------------------------
__global__ void scan_partial(int M) {
    __shared__ int wsum[32];
    int tid  = threadIdx.x;
    int gi   = blockIdx.x * SCAN_BLK + tid;
    int lane = tid & 31;
    int wid  = tid >> 5;

    int v = (gi < M) ? g_off[gi] : 0;

    int x = v;
#pragma unroll
    for (int o = 1; o < 32; o <<= 1) {
        int y = __shfl_up_sync(0xFFFFFFFFu, x, o);
        if (lane >= o) x += y;
    }
    if (lane == 31) wsum[wid] = x;
    __syncthreads();

    if (wid == 0) {
        int w = wsum[lane];
#pragma unroll
        for (int o = 1; o < 32; o <<= 1) {
            int y = __shfl_up_sync(0xFFFFFFFFu, w, o);
            if (lane >= o) w += y;
        }
        wsum[lane] = w;
    }
    __syncthreads();

    int incl = x + (wid > 0 ? wsum[wid - 1] : 0);
    int excl = incl - v;
    if (gi < M) g_off[gi] = excl;
    if (tid == SCAN_BLK - 1) g_bsum[blockIdx.x] = incl;
}

__global__ void scan_bsums(int nb) {
    __shared__ int s[MAX_SBLKS];
    int lane = threadIdx.x;
    if (lane < MAX_SBLKS) s[lane] = (lane < nb) ? g_bsum[lane] : 0;
    __syncthreads();
    if (lane == 0) {
        int run = 0;
        for (int i = 0; i < nb; i++) { int t = s[i]; s[i] = run; run += t; }
        s[nb] = run;
    }
    __syncthreads();
    if (lane <= nb) g_bsum[lane] = s[lane];
}

__global__ void scan_add(int M) {
    int tid = threadIdx.x;
    int gi  = blockIdx.x * SCAN_BLK + tid;
    if (gi < M) {
        int o = g_off[gi] + g_bsum[blockIdx.x];
        g_off[gi] = o;
        g_cur[gi] = o;
    }
    if (gi == M) {
        int nb = (M + SCAN_BLK - 1) / SCAN_BLK;
        g_off[M] = g_bsum[nb];
    }
}

__global__ void scatter_kernel(const void* __restrict__ ei, int E, int M) {
    int t = blockIdx.x * blockDim.x + threadIdx.x;
    if (t >= E) return;
    int src = load_idx(ei, t, M);
    int dst = load_idx(ei, (long long)E + t, M);
    int pos = atomicAdd(&g_cur[dst], 1);
    g_srcs[pos] = src;
}

// ---------------------------------------------------------------------------
// tf32 tensor-core GEMM with 3-term hi/lo split (~fp32 accuracy):
//   C[M,128] = A[M,128] @ W[128,128]^T + bias (+relu)
// 256 thr = 8 warps; warp w owns rows [w*16, w*16+16) x all 128 cols
// (16 m16n8 accumulators). W in padded smem (stride 132), A slabs of 32 k
// (stride 36). mma.sync.aligned.m16n8k8.row.col.f32.tf32.tf32.f32.
// blockIdx.y selects among up to 3 (W, bias, C) triples (fused QKV).
// ---------------------------------------------------------------------------
#define WS_STRIDE 132
#define AS_STRIDE 36
#define GEMM_SMEM ((128 * WS_STRIDE + 128 * AS_STRIDE) * 4)

__device__ __forceinline__ unsigned f2tf32(float x) {
    unsigned r;
    asm("cvt.rna.tf32.f32 %0, %1;" : "=r"(r) : "f"(x));
    return r;
}

__device__ __forceinline__ void mma_tf32(float* d,
                                         unsigned a0, unsigned a1,
                                         unsigned a2, unsigned a3,
                                         unsigned b0, unsigned b1) {
    asm("mma.sync.aligned.m16n8k8.row.col.f32.tf32.tf32.f32 "
        "{%0,%1,%2,%3}, {%4,%5,%6,%7}, {%8,%9}, {%0,%1,%2,%3};"
        : "+f"(d[0]), "+f"(d[1]), "+f"(d[2]), "+f"(d[3])
        : "r"(a0), "r"(a1), "r"(a2), "r"(a3), "r"(b0), "r"(b1));
}

__global__ __launch_bounds__(256, 2)
void gemm_tf32_kernel(const float* __restrict__ A, int M,
                      const float* __restrict__ Wa, const float* __restrict__ Wb,
                      const float* __restrict__ Wc,
                      const float* __restrict__ ba, const float* __restrict__ bb,
                      const float* __restrict__ bc,
                      float* __restrict__ Ca, float* __restrict__ Cb,
                      float* __restrict__ Cc,
                      int relu)
{
    extern __shared__ float smem[];
    float* Ws = smem;                       // [128][WS_STRIDE]
    float* As = smem + 128 * WS_STRIDE;     // [128][AS_STRIDE]

    const float* W;
    const float* bias;
    float*       C;
    if (blockIdx.y == 0)      { W = Wa; bias = ba; C = Ca; }
    else if (blockIdx.y == 1) { W = Wb; bias = bb; C = Cb; }
    else                      { W = Wc; bias = bc; C = Cc; }

    int tid  = threadIdx.x;
    int wid  = tid >> 5;
    int lane = tid & 31;
    int g    = lane >> 2;      // group id 0..7
    int c    = lane & 3;       // thread-in-group 0..3
    int m0   = blockIdx.x * 128;

    // load W (128x128) into padded smem: 16 float4 per thread
#pragma unroll
    for (int i = 0; i < 16; i++) {
        int i4  = tid + i * 256;        // 0..4095
        int row = i4 >> 5;              // 0..127
        int c4  = (i4 & 31) * 4;        // 0..124
        float4 w = *(const float4*)(W + (size_t)row * 128 + c4);
        float* p = Ws + row * WS_STRIDE + c4;
        p[0] = w.x; p[1] = w.y; p[2] = w.z; p[3] = w.w;
    }

    float acc[16][4];
#pragma unroll
    for (int t = 0; t < 16; t++)
#pragma unroll
        for (int j = 0; j < 4; j++) acc[t][j] = 0.f;

    int r0 = wid * 16 + g;     // warp-local A rows r0, r0+8

    for (int slab = 0; slab < 4; slab++) {
        // load A slab: rows 0..127, cols [slab*32, slab*32+32)
        __syncthreads();
#pragma unroll
        for (int i = 0; i < 4; i++) {
            int idx = tid + i * 256;    // 0..1023 float4 slots
            int row = idx >> 3;         // 0..127
            int kq  = idx & 7;          // 0..7
            float4 v = make_float4(0.f, 0.f, 0.f, 0.f);
            int m = m0 + row;
            if (m < M)
                v = *(const float4*)(A + (size_t)m * 128 + slab * 32 + kq * 4);
            float* p = As + row * AS_STRIDE + kq * 4;
            p[0] = v.x; p[1] = v.y; p[2] = v.z; p[3] = v.w;
        }
        __syncthreads();

#pragma unroll
        for (int kk = 0; kk < 4; kk++) {
            int kc = kk * 8 + c;
            // A fragment (rows r0, r0+8; cols kc, kc+4)
            float a0f = As[r0 * AS_STRIDE + kc];
            float a1f = As[(r0 + 8) * AS_STRIDE + kc];
            float a2f = As[r0 * AS_STRIDE + kc + 4];
            float a3f = As[(r0 + 8) * AS_STRIDE + kc + 4];
            unsigned a0h = f2tf32(a0f), a1h = f2tf32(a1f);
            unsigned a2h = f2tf32(a2f), a3h = f2tf32(a3f);
            unsigned a0l = f2tf32(a0f - __uint_as_float(a0h));
            unsigned a1l = f2tf32(a1f - __uint_as_float(a1h));
            unsigned a2l = f2tf32(a2f - __uint_as_float(a2h));
            unsigned a3l = f2tf32(a3f - __uint_as_float(a3h));

            int kg = slab * 32 + kk * 8;   // global k base of this step
#pragma unroll
            for (int nt = 0; nt < 16; nt++) {
                int n = nt * 8 + g;
                // B fragment: B[k][n] = W[n][k] -> b0=W[n][kg+c], b1=W[n][kg+c+4]
                float b0f = Ws[n * WS_STRIDE + kg + c];
                float b1f = Ws[n * WS_STRIDE + kg + c + 4];
                unsigned b0h = f2tf32(b0f), b1h = f2tf32(b1f);
                unsigned b0l = f2tf32(b0f - __uint_as_float(b0h));
                unsigned b1l = f2tf32(b1f - __uint_as_float(b1h));

                mma_tf32(acc[nt], a0h, a1h, a2h, a3h, b0l, b1l);  // hi*lo
                mma_tf32(acc[nt], a0l, a1l, a2l, a3l, b0h, b1h);  // lo*hi
                mma_tf32(acc[nt], a0h, a1h, a2h, a3h, b0h, b1h);  // hi*hi
            }
        }
    }

    // epilogue: bias + optional relu; rows m0+r0, m0+r0+8; cols nt*8+2c(+1)
    int mA = m0 + r0;
    int mB = mA + 8;
#pragma unroll
    for (int nt = 0; nt < 16; nt++) {
        int n = nt * 8 + 2 * c;
        float bx = bias[n], by = bias[n + 1];
        float2 oA = make_float2(acc[nt][0] + bx, acc[nt][1] + by);
        float2 oB = make_float2(acc[nt][2] + bx, acc[nt][3] + by);
        if (relu) {
            oA.x = fmaxf(oA.x, 0.f); oA.y = fmaxf(oA.y, 0.f);
            oB.x = fmaxf(oB.x, 0.f); oB.y = fmaxf(oB.y, 0.f);
        }
        if (mA < M) *(float2*)(C + (size_t)mA * 128 + n) = oA;
        if (mB < M) *(float2*)(C + (size_t)mB * 128 + n) = oB;
    }
}

// ---------------------------------------------------------------------------
// Warp per dst node: softmax-weighted aggregation of V[src] over CSR edges.
// ---------------------------------------------------------------------------
__device__ __forceinline__ void edge_step(int sj, const float4& q,
                                          float4& acc, float& ssum, int lane)
{
    float4 k = ((const float4*)(g_K + (size_t)sj * 128))[lane];
    float4 v = ((const float4*)(g_V + (size_t)sj * 128))[lane];
    float part = q.x * k.x + q.y * k.y + q.z * k.z + q.w * k.w;
    part += __shfl_xor_sync(0xFFFFFFFFu, part, 1);
    part += __shfl_xor_sync(0xFFFFFFFFu, part, 2);
    part += __shfl_xor_sync(0xFFFFFFFFu, part, 4);
    float p = expf(part * 0.17677669529663687f);
    acc.x = fmaf(p, v.x, acc.x);
    acc.y = fmaf(p, v.y, acc.y);
    acc.z = fmaf(p, v.z, acc.z);
    acc.w = fmaf(p, v.w, acc.w);
    ssum += p;
}

__global__ __launch_bounds__(256)
void aggregate_kernel(int M)
{
    int w    = (int)(((long long)blockIdx.x * blockDim.x + threadIdx.x) >> 5);
    int lane = threadIdx.x & 31;
    if (w >= M) return;

    int start = g_off[w];
    int end   = g_cur[w];    // == g_off[w+1] after scatter

    float4 q = ((const float4*)(g_Q + (size_t)w * 128))[lane];
    float4 acc = make_float4(0.f, 0.f, 0.f, 0.f);
    float ssum = 0.f;

    int i = start;
    for (; i + 32 <= end; i += 32) {
        int s = g_srcs[i + lane];
#pragma unroll 4
        for (int j = 0; j < 32; j++) {
            int sj = __shfl_sync(0xFFFFFFFFu, s, j);
            edge_step(sj, q, acc, ssum, lane);
        }
    }
    if (i < end) {
        int rem = end - i;
        int s = (lane < rem) ? g_srcs[i + lane] : 0;
        for (int j = 0; j < rem; j++) {
            int sj = __shfl_sync(0xFFFFFFFFu, s, j);
            edge_step(sj, q, acc, ssum, lane);
        }
    }

    float inv = 1.f / (ssum + 1e-8f);
    float4 o = make_float4(acc.x * inv, acc.y * inv, acc.z * inv, acc.w * inv);
    ((float4*)(g_agg + (size_t)w * 128))[lane] = o;
}

// ---------------------------------------------------------------------------
extern "C" void kernel_launch(void* const* d_in, const int* in_sizes, int n_in,
                              void* d_out, int out_size)
{
    const float* x  = (const float*)d_in[0];
    const void*  ei = d_in[1];
    const float* Wq = (const float*)d_in[2];
    const float* bq = (const float*)d_in[3];
    const float* Wk = (const float*)d_in[4];
    const float* bk = (const float*)d_in[5];
    const float* Wv = (const float*)d_in[6];
    const float* bv = (const float*)d_in[7];
    const float* Wo = (const float*)d_in[8];
    const float* bo = (const float*)d_in[9];
    float*       out = (float*)d_out;

    int M = in_sizes[0] / 128;   // nodes
    int E = in_sizes[1] / 2;     // edges

    float *pQ, *pK, *pV, *pAgg;
    cudaGetSymbolAddress((void**)&pQ,   g_Q);
    cudaGetSymbolAddress((void**)&pK,   g_K);
    cudaGetSymbolAddress((void**)&pV,   g_V);
    cudaGetSymbolAddress((void**)&pAgg, g_agg);

    cudaFuncSetAttribute(gemm_tf32_kernel,
                         cudaFuncAttributeMaxDynamicSharedMemorySize, GEMM_SMEM);

    int nb = (M + SCAN_BLK - 1) / SCAN_BLK;   // 49 for M=50000

    detect_kernel<<<1, 32>>>((const unsigned*)ei);
    zero_deg<<<(M + 255) / 256, 256>>>(M);
    hist_kernel<<<(E + 255) / 256, 256>>>(ei, E, M);
    scan_partial<<<nb, SCAN_BLK>>>(M);
    scan_bsums<<<1, MAX_SBLKS>>>(nb);
    scan_add<<<nb + 1, SCAN_BLK>>>(M);
    scatter_kernel<<<(E + 255) / 256, 256>>>(ei, E, M);

    dim3 gqkv((M + 127) / 128, 3);
    gemm_tf32_kernel<<<gqkv, 256, GEMM_SMEM>>>(x, M, Wq, Wk, Wv, bq, bk, bv,
                                               pQ, pK, pV, 0);

    long long wt = (long long)M * 32;
    aggregate_kernel<<<(int)((wt + 255) / 256), 256>>>(M);

    dim3 gout((M + 127) / 128, 1);
    gemm_tf32_kernel<<<gout, 256, GEMM_SMEM>>>(pAgg, M, Wo, Wo, Wo, bo, bo, bo,
                                               out, out, out, 1);
}